// round 5
// baseline (speedup 1.0000x reference)
#include <cuda_runtime.h>
#include <cuda.h>
#include <cstdint>

#define OUT_F 4096
#define IN_F  4096
#define M_TOT 8192

#define BM 256
#define BN 256
#define KC 32                    // K floats per stage (128 bytes per row)
#define NKI (IN_F / KC)          // 128 k-iterations
#define STAGES 3
#define STAGE_BYTES 65536        // A 32KB + B 32KB
#define SMEM_STAGE0 1024
#define SMEM_TOTAL (SMEM_STAGE0 + STAGES * STAGE_BYTES)   // 197632
#define NT 128
#define CSZ 8                    // cluster size (multicast width for A)
#define MCAST_MASK 0xFFu

// idesc: dtype=F32(1<<4), atype=TF32(2<<7), btype=TF32(2<<10), N/8<<17, M/16<<24
#define MMA_IDESC ((1u<<4) | (2u<<7) | (2u<<10) | ((BN/8u)<<17) | ((128u/16u)<<24))

// SW128 K-major smem descriptor base: layout=2, version=1, SBO=64, LBO=1
#define DESC_BASE ((2ull<<61) | (1ull<<46) | (64ull<<32) | (1ull<<16))
#define MAKE_DESC(a) (DESC_BASE | ((uint64_t)((a) >> 4) & 0x3FFF))

__device__ float g_W[(size_t)OUT_F * IN_F];   // dequantized, tf32-RNA-rounded
__device__ float g_X[(size_t)M_TOT * IN_F];   // x, tf32-RNA-rounded

// ---------------------------------------------------------------- helpers
__device__ __forceinline__ uint32_t f2tf32(float f) {
    uint32_t r;
    asm("cvt.rna.tf32.f32 %0, %1;" : "=r"(r) : "f"(f));
    return r;
}
__device__ __forceinline__ uint32_t smem_u32(const void* p) {
    uint32_t a;
    asm("{ .reg .u64 t; cvta.to.shared.u64 t, %1; cvt.u32.u64 %0, t; }" : "=r"(a) : "l"(p));
    return a;
}
#define MBARRIER_INIT(a, c) \
    asm volatile("mbarrier.init.shared.b64 [%0], %1;" :: "r"(a), "r"(c) : "memory")
#define MBARRIER_INVAL(a) \
    asm volatile("mbarrier.inval.shared.b64 [%0];" :: "r"(a) : "memory")
#define MBARRIER_EXPECT_TX(a, b) \
    asm volatile("mbarrier.arrive.expect_tx.shared.b64 _, [%0], %1;" :: "r"(a), "r"((uint32_t)(b)) : "memory")
#define MBARRIER_WAIT_PARITY(addr, par) do {                                   \
    uint32_t _m = (addr); uint32_t _p = (par); uint32_t _d;                    \
    asm volatile("{\n\t.reg .pred p;\n\t"                                      \
        "mbarrier.try_wait.parity.acquire.cta.shared::cta.b64 p, [%1], %2;\n\t"\
        "selp.b32 %0, 1, 0, p;\n\t}"                                           \
        : "=r"(_d) : "r"(_m), "r"(_p) : "memory");                             \
    if (!_d) {                                                                  \
        asm volatile("{\n\t.reg .pred P1;\n\t"                                 \
            "WL_%=:\n\t"                                                       \
            "mbarrier.try_wait.parity.acquire.cta.shared::cta.b64 P1, [%0], %1, 0x989680;\n\t" \
            "@P1 bra.uni WD_%=;\n\t"                                           \
            "bra.uni WL_%=;\n\t"                                               \
            "WD_%=:\n\t}"                                                      \
            :: "r"(_m), "r"(_p) : "memory");                                   \
    }                                                                           \
} while (0)
#define CLUSTER_ARRIVE() asm volatile("barrier.cluster.arrive.aligned;" ::: "memory")
#define CLUSTER_WAIT()   asm volatile("barrier.cluster.wait.aligned;" ::: "memory")

// ---------------------------------------------------------------- prepass
__global__ void prepass_kernel(const float* __restrict__ x,
                               const int* __restrict__ packed,
                               const float* __restrict__ scales,
                               const float* __restrict__ offsets) {
    if (blockIdx.x < 32768) {
        size_t i = (size_t)blockIdx.x * blockDim.x + threadIdx.x;  // float4 index
        float4 v = reinterpret_cast<const float4*>(x)[i];
        float4 o;
        o.x = __uint_as_float(f2tf32(v.x));
        o.y = __uint_as_float(f2tf32(v.y));
        o.z = __uint_as_float(f2tf32(v.z));
        o.w = __uint_as_float(f2tf32(v.w));
        reinterpret_cast<float4*>(g_X)[i] = o;
    } else {
        int i = (blockIdx.x - 32768) * blockDim.x + threadIdx.x;  // packed index
        int p = packed[i];
        int g = i >> 6;
        float s = scales[g];
        float o = offsets[g];
        float2 out;
        out.x = __uint_as_float(f2tf32((float)(p & 0xF) * s + o));
        out.y = __uint_as_float(f2tf32((float)((p >> 4) & 0xF) * s + o));
        *reinterpret_cast<float2*>(&g_W[2 * (size_t)i]) = out;
    }
}

// ---------------------------------------------------------------- arch gate
// tcgen05/TMA-multicast only exist in the sm_103a cubin; the harness's plain
// compute_103 PTX fallback compiles an empty body.
#if defined(__CUDA_ARCH_FEAT_SM103_ALL)
#define HAS_TCGEN05 1
#else
#define HAS_TCGEN05 0
#endif

#if HAS_TCGEN05
#define TCGEN05_ALLOC(sa, n) \
    asm volatile("tcgen05.alloc.cta_group::1.sync.aligned.shared::cta.b32 [%0], %1;" \
                 :: "r"(sa), "r"((uint32_t)(n)) : "memory")
#define TCGEN05_DEALLOC(t, n) \
    asm volatile("tcgen05.dealloc.cta_group::1.sync.aligned.b32 %0, %1;" :: "r"(t), "r"((uint32_t)(n)))
#define TCGEN05_RELINQUISH() \
    asm volatile("tcgen05.relinquish_alloc_permit.cta_group::1.sync.aligned;")
#define TCGEN05_COMMIT(mb) \
    asm volatile("tcgen05.commit.cta_group::1.mbarrier::arrive::one.shared::cluster.b64 [%0];" \
                 :: "r"(mb) : "memory")
#define TCGEN05_COMMIT_MC(mb, mask) \
    asm volatile("tcgen05.commit.cta_group::1.mbarrier::arrive::one.shared::cluster.multicast::cluster.b64 [%0], %1;" \
                 :: "r"(mb), "h"((uint16_t)(mask)) : "memory")
#define TCGEN05_FENCE_AFTER() asm volatile("tcgen05.fence::after_thread_sync;" ::: "memory")
#define TCGEN05_FENCE_BEFORE() asm volatile("tcgen05.fence::before_thread_sync;" ::: "memory")
#define TCGEN05_WAIT_LD() asm volatile("tcgen05.wait::ld.sync.aligned;" ::: "memory")

#define TMA_LOAD_2D(dst, map, cx, cy, mb) \
    asm volatile("cp.async.bulk.tensor.2d.shared::cta.global.tile.mbarrier::complete_tx::bytes " \
        "[%0], [%1, {%2, %3}], [%4];" \
        :: "r"(dst), "l"(map), "r"(cx), "r"(cy), "r"(mb) : "memory")
#define TMA_LOAD_2D_MC(dst, map, cx, cy, mb, mask) \
    asm volatile("cp.async.bulk.tensor.2d.shared::cluster.global.tile.mbarrier::complete_tx::bytes.multicast::cluster " \
        "[%0], [%1, {%2, %3}], [%4], %5;" \
        :: "r"(dst), "l"(map), "r"(cx), "r"(cy), "r"(mb), "h"((uint16_t)(mask)) : "memory")

#define LDTM_X32(r, a) \
    asm volatile("tcgen05.ld.sync.aligned.32x32b.x32.b32 "                     \
        "{%0,%1,%2,%3,%4,%5,%6,%7,%8,%9,%10,%11,%12,%13,%14,%15,"              \
        "%16,%17,%18,%19,%20,%21,%22,%23,%24,%25,%26,%27,%28,%29,%30,%31}, [%32];" \
        : "=r"((r)[0]), "=r"((r)[1]), "=r"((r)[2]), "=r"((r)[3]),              \
          "=r"((r)[4]), "=r"((r)[5]), "=r"((r)[6]), "=r"((r)[7]),              \
          "=r"((r)[8]), "=r"((r)[9]), "=r"((r)[10]), "=r"((r)[11]),            \
          "=r"((r)[12]), "=r"((r)[13]), "=r"((r)[14]), "=r"((r)[15]),          \
          "=r"((r)[16]), "=r"((r)[17]), "=r"((r)[18]), "=r"((r)[19]),          \
          "=r"((r)[20]), "=r"((r)[21]), "=r"((r)[22]), "=r"((r)[23]),          \
          "=r"((r)[24]), "=r"((r)[25]), "=r"((r)[26]), "=r"((r)[27]),          \
          "=r"((r)[28]), "=r"((r)[29]), "=r"((r)[30]), "=r"((r)[31])           \
        : "r"(a))

__device__ __forceinline__ void mma_tf32_ss(uint32_t d, uint64_t ad, uint64_t bd,
                                            uint32_t idesc, uint32_t en) {
    asm volatile(
        "{\n\t.reg .pred p;\n\tsetp.ne.u32 p, %5, 0;\n\t"
        "tcgen05.mma.cta_group::1.kind::tf32 [%0], %1, %2, %3, {%4,%4,%4,%4}, p;\n\t}"
        :: "r"(d), "l"(ad), "l"(bd), "r"(idesc), "r"(0u), "r"(en) : "memory");
}
#endif  // HAS_TCGEN05

// mbarrier layout: full[s] at sb+8+s*16, empty[s] at sb+16+s*16, done at sb+8+S*16
#define FULLB(sb, s)  ((sb) + 8 + (s) * 16)
#define EMPTYB(sb, s) ((sb) + 16 + (s) * 16)
#define DONEB(sb)     ((sb) + 8 + STAGES * 16)

__global__ void __launch_bounds__(NT, 1) __cluster_dims__(CSZ, 1, 1)
gemm_tc(const __grid_constant__ CUtensorMap tmx,
        const __grid_constant__ CUtensorMap tmw,
        const float* __restrict__ bias, float* __restrict__ Y) {
#if HAS_TCGEN05
    extern __shared__ __align__(1024) char smem[];
    const uint32_t sb = smem_u32(smem);
    const int tid = threadIdx.x;
    const int wid = tid >> 5;
    const int lane = tid & 31;
    const int m0 = blockIdx.y * BM;
    const int n0 = blockIdx.x * BN;
    uint32_t rank;
    asm("mov.u32 %0, %%cluster_ctarank;" : "=r"(rank));

    if (wid == 0) TCGEN05_ALLOC(sb, 512);
    if (tid == 0) {
#pragma unroll
        for (int s = 0; s < STAGES; s++) {
            MBARRIER_INIT(FULLB(sb, s), 1);     // expect_tx arrival only
            MBARRIER_INIT(EMPTYB(sb, s), CSZ);  // commit-multicast from all 8 CTAs
        }
        MBARRIER_INIT(DONEB(sb), 1);
    }
    __syncthreads();
    // all cluster mbarriers visible before any multicast targets them
    CLUSTER_ARRIVE();
    CLUSTER_WAIT();

    uint32_t tmem;
    asm volatile("ld.shared.b32 %0, [%1];" : "=r"(tmem) : "r"(sb));

    if (tid == 0) {
        // -------- driver: TMA producer + MMA issuer in one thread --------
        // prologue: issue loads for stages 0..STAGES-1
#pragma unroll
        for (int p = 0; p < STAGES; p++) {
            const uint32_t abase = sb + SMEM_STAGE0 + p * STAGE_BYTES;
            const uint32_t bbase = abase + 32768;
            MBARRIER_EXPECT_TX(FULLB(sb, p), STAGE_BYTES);
            // A slice (32 rows, 4KB) multicast to all 8 CTAs
            TMA_LOAD_2D_MC(abase + rank * 4096, &tmx,
                           p * KC, m0 + (int)rank * 32, FULLB(sb, p), MCAST_MASK);
            // B full tile (256 rows, 32KB) local
            TMA_LOAD_2D(bbase, &tmw, p * KC, n0, FULLB(sb, p));
        }

        for (int kt = 0; kt < NKI; kt++) {
            const int b = kt % STAGES;
            MBARRIER_WAIT_PARITY(FULLB(sb, b), (uint32_t)((kt / STAGES) & 1));
            const uint32_t ss = sb + SMEM_STAGE0 + b * STAGE_BYTES;
            const uint64_t a0 = MAKE_DESC(ss);
            const uint64_t a1 = MAKE_DESC(ss + 16384);   // A rows 128-255
            const uint64_t bd = MAKE_DESC(ss + 32768);
#pragma unroll
            for (int ks = 0; ks < 4; ks++) {             // 4 x K=8 within 128B row
                const uint32_t en = (kt > 0 || ks > 0) ? 1u : 0u;
                mma_tf32_ss(tmem,       a0 + ks * 2, bd + ks * 2, MMA_IDESC, en);
                mma_tf32_ss(tmem + 256, a1 + ks * 2, bd + ks * 2, MMA_IDESC, en);
            }
            // when these MMAs complete, stage b is consumable-free in ALL CTAs
            TCGEN05_COMMIT_MC(EMPTYB(sb, b), MCAST_MASK);

            const int nk = kt + STAGES;
            if (nk < NKI) {
                // wait all 8 CTAs done with round kt/STAGES of buffer b, then refill
                MBARRIER_WAIT_PARITY(EMPTYB(sb, b), (uint32_t)((kt / STAGES) & 1));
                const uint32_t abase = sb + SMEM_STAGE0 + b * STAGE_BYTES;
                const uint32_t bbase = abase + 32768;
                MBARRIER_EXPECT_TX(FULLB(sb, b), STAGE_BYTES);
                TMA_LOAD_2D_MC(abase + rank * 4096, &tmx,
                               nk * KC, m0 + (int)rank * 32, FULLB(sb, b), MCAST_MASK);
                TMA_LOAD_2D(bbase, &tmw, nk * KC, n0, FULLB(sb, b));
            }
        }
        TCGEN05_COMMIT(DONEB(sb));   // in-order: fires when ALL local MMAs done
    }

    // -------- epilogue: 4 warps read TMEM, add bias, store --------
    MBARRIER_WAIT_PARITY(DONEB(sb), 0u);
    TCGEN05_FENCE_AFTER();
#pragma unroll
    for (int half = 0; half < 2; half++) {
        const int m = m0 + half * 128 + wid * 32 + lane;
        float* yrow = Y + (size_t)m * OUT_F + n0;
#pragma unroll
        for (int c0 = 0; c0 < 256; c0 += 32) {
            uint32_t r[32];
            LDTM_X32(r, tmem + half * 256 + c0);
            TCGEN05_WAIT_LD();
            const float* bp = bias + n0 + c0;
#pragma unroll
            for (int j = 0; j < 32; j += 4) {
                float4 v;
                v.x = __uint_as_float(r[j + 0]) + bp[j + 0];
                v.y = __uint_as_float(r[j + 1]) + bp[j + 1];
                v.z = __uint_as_float(r[j + 2]) + bp[j + 2];
                v.w = __uint_as_float(r[j + 3]) + bp[j + 3];
                *reinterpret_cast<float4*>(yrow + c0 + j) = v;
            }
        }
    }
    TCGEN05_FENCE_BEFORE();

    __syncthreads();
    if (tid == 0) {
#pragma unroll
        for (int s = 0; s < STAGES; s++) {
            MBARRIER_INVAL(FULLB(sb, s));
            MBARRIER_INVAL(EMPTYB(sb, s));
        }
        MBARRIER_INVAL(DONEB(sb));
    }
    __syncthreads();
    if (wid == 0) {
        TCGEN05_RELINQUISH();
        TCGEN05_DEALLOC(tmem, 512);
    }
    // no CTA exits while peers may still multicast/commit into its smem
    CLUSTER_ARRIVE();
    CLUSTER_WAIT();
#endif  // HAS_TCGEN05
}

// ---------------------------------------------------------------- launch
typedef CUresult (*tmap_encode_fn)(
    CUtensorMap*, CUtensorMapDataType, cuuint32_t, void*,
    const cuuint64_t*, const cuuint64_t*, const cuuint32_t*, const cuuint32_t*,
    CUtensorMapInterleave, CUtensorMapSwizzle, CUtensorMapL2promotion,
    CUtensorMapFloatOOBfill);

extern "C" void kernel_launch(void* const* d_in, const int* in_sizes, int n_in,
                              void* d_out, int out_size) {
    const float* x       = (const float*)d_in[0];
    const int*   packed  = (const int*)d_in[1];
    const float* scales  = (const float*)d_in[2];
    const float* offsets = (const float*)d_in[3];
    const float* bias    = (const float*)d_in[4];
    float* out = (float*)d_out;

    static CUtensorMap tmx, tmw;
    static bool inited = false;
    if (!inited) {
        void* fn = nullptr;
        cudaDriverEntryPointQueryResult qr;
        cudaGetDriverEntryPointByVersion("cuTensorMapEncodeTiled", &fn, 12050,
                                         cudaEnableDefault, &qr);
        tmap_encode_fn enc = (tmap_encode_fn)fn;
        void *px = nullptr, *pw = nullptr;
        cudaGetSymbolAddress(&px, g_X);
        cudaGetSymbolAddress(&pw, g_W);

        cuuint64_t dimsx[2] = {IN_F, M_TOT};
        cuuint64_t strdx[1] = {IN_F * sizeof(float)};
        cuuint32_t boxA[2]  = {KC, 32};          // 128B x 32 rows = 4KB slice
        cuuint32_t es[2]    = {1, 1};
        enc(&tmx, CU_TENSOR_MAP_DATA_TYPE_FLOAT32, 2, px, dimsx, strdx, boxA, es,
            CU_TENSOR_MAP_INTERLEAVE_NONE, CU_TENSOR_MAP_SWIZZLE_128B,
            CU_TENSOR_MAP_L2_PROMOTION_L2_128B, CU_TENSOR_MAP_FLOAT_OOB_FILL_NONE);

        cuuint64_t dimsw[2] = {IN_F, OUT_F};
        cuuint64_t strdw[1] = {IN_F * sizeof(float)};
        cuuint32_t boxB[2]  = {KC, 256};         // 128B x 256 rows = 32KB tile
        enc(&tmw, CU_TENSOR_MAP_DATA_TYPE_FLOAT32, 2, pw, dimsw, strdw, boxB, es,
            CU_TENSOR_MAP_INTERLEAVE_NONE, CU_TENSOR_MAP_SWIZZLE_128B,
            CU_TENSOR_MAP_L2_PROMOTION_L2_128B, CU_TENSOR_MAP_FLOAT_OOB_FILL_NONE);

        cudaFuncSetAttribute(gemm_tc, cudaFuncAttributeMaxDynamicSharedMemorySize,
                             SMEM_TOTAL);
        inited = true;
    }

    // fused prepass: X tf32-round (32768 blocks) + W dequant (32768 blocks)
    prepass_kernel<<<65536, 256>>>(x, packed, scales, offsets);

    // main GEMM: 256x256 tiles, 8-CTA cluster, TMA-multicast A
    dim3 grid(OUT_F / BN, M_TOT / BM);   // (16, 32); x divisible by CSZ=8
    gemm_tc<<<grid, NT, SMEM_TOTAL>>>(tmx, tmw, bias, out);
}

// round 6
// speedup vs baseline: 2.4869x; 2.4869x over previous
#include <cuda_runtime.h>
#include <cuda_fp16.h>
#include <cstdint>

#define OUT_F 4096
#define IN_F  4096
#define M_TOT 8192

#define BM 256
#define BN 256
#define KC 64                    // K halves per stage (128 bytes per row)
#define NKI (IN_F / KC)          // 64 k-iterations
#define STAGES 3
#define STAGE_BYTES 65536        // A 32KB (256 rows x 128B) + B 32KB
#define SMEM_STAGE0 1024
#define SMEM_TOTAL (SMEM_STAGE0 + STAGES * STAGE_BYTES)   // 197632
#define NT 384                   // warps 0-7 producers, warp8 MMA, warps 8-11 epilogue

// idesc kind::f16: dtype=F32(1<<4), atype=FP16(0<<7), btype=FP16(0<<10),
// N/8<<17, M/16<<24
#define MMA_IDESC ((1u<<4) | ((BN/8u)<<17) | ((128u/16u)<<24))

// SW128 K-major smem descriptor base: layout=2, version=1, SBO=64, LBO=1
#define DESC_BASE ((2ull<<61) | (1ull<<46) | (64ull<<32) | (1ull<<16))
#define MAKE_DESC(a) (DESC_BASE | ((uint64_t)((a) >> 4) & 0x3FFF))

__device__ __half g_W[(size_t)OUT_F * IN_F];   // dequantized fp16
__device__ __half g_X[(size_t)M_TOT * IN_F];   // x rounded to fp16

// ---------------------------------------------------------------- helpers
__device__ __forceinline__ uint32_t smem_u32(const void* p) {
    uint32_t a;
    asm("{ .reg .u64 t; cvta.to.shared.u64 t, %1; cvt.u32.u64 %0, t; }" : "=r"(a) : "l"(p));
    return a;
}
#define CP_ASYNC16(dst, src) \
    asm volatile("cp.async.cg.shared.global [%0], [%1], 16;" :: "r"(dst), "l"(src) : "memory")
#define CP_ASYNC_MBAR_ARRIVE(mb) \
    asm volatile("cp.async.mbarrier.arrive.noinc.shared.b64 [%0];" :: "r"(mb) : "memory")

#define MBARRIER_INIT(a, c) \
    asm volatile("mbarrier.init.shared.b64 [%0], %1;" :: "r"(a), "r"(c) : "memory")
#define MBARRIER_INVAL(a) \
    asm volatile("mbarrier.inval.shared.b64 [%0];" :: "r"(a) : "memory")
#define MBARRIER_WAIT_PARITY(addr, par) do {                                   \
    uint32_t _m = (addr); uint32_t _p = (par); uint32_t _d;                    \
    asm volatile("{\n\t.reg .pred p;\n\t"                                      \
        "mbarrier.try_wait.parity.acquire.cta.shared::cta.b64 p, [%1], %2;\n\t"\
        "selp.b32 %0, 1, 0, p;\n\t}"                                           \
        : "=r"(_d) : "r"(_m), "r"(_p) : "memory");                             \
    if (!_d) {                                                                  \
        asm volatile("{\n\t.reg .pred P1;\n\t"                                 \
            "WL_%=:\n\t"                                                       \
            "mbarrier.try_wait.parity.acquire.cta.shared::cta.b64 P1, [%0], %1, 0x989680;\n\t" \
            "@P1 bra.uni WD_%=;\n\t"                                           \
            "bra.uni WL_%=;\n\t"                                               \
            "WD_%=:\n\t}"                                                      \
            :: "r"(_m), "r"(_p) : "memory");                                   \
    }                                                                           \
} while (0)

// ---------------------------------------------------------------- prepass
// blocks [0, 32768): round X to fp16 into g_X
// blocks [32768, 65536): dequant packed 4-bit -> g_W (fp16)
__global__ void prepass_kernel(const float* __restrict__ x,
                               const int* __restrict__ packed,
                               const float* __restrict__ scales,
                               const float* __restrict__ offsets) {
    if (blockIdx.x < 32768) {
        size_t i = (size_t)blockIdx.x * blockDim.x + threadIdx.x;  // float4 index
        float4 v = reinterpret_cast<const float4*>(x)[i];
        __half2 h0 = __floats2half2_rn(v.x, v.y);
        __half2 h1 = __floats2half2_rn(v.z, v.w);
        uint2 o;
        o.x = *reinterpret_cast<uint32_t*>(&h0);
        o.y = *reinterpret_cast<uint32_t*>(&h1);
        reinterpret_cast<uint2*>(g_X)[i] = o;
    } else {
        int i = (blockIdx.x - 32768) * blockDim.x + threadIdx.x;  // packed index
        int p = packed[i];
        int g = i >> 6;
        float s = scales[g];
        float o = offsets[g];
        __half2 h = __floats2half2_rn((float)(p & 0xF) * s + o,
                                      (float)((p >> 4) & 0xF) * s + o);
        reinterpret_cast<__half2*>(g_W)[i] = h;
    }
}

// ---------------------------------------------------------------- arch gate
#if defined(__CUDA_ARCH_FEAT_SM103_ALL)
#define HAS_TCGEN05 1
#else
#define HAS_TCGEN05 0
#endif

#if HAS_TCGEN05
#define TCGEN05_ALLOC(sa, n) \
    asm volatile("tcgen05.alloc.cta_group::1.sync.aligned.shared::cta.b32 [%0], %1;" \
                 :: "r"(sa), "r"((uint32_t)(n)) : "memory")
#define TCGEN05_DEALLOC(t, n) \
    asm volatile("tcgen05.dealloc.cta_group::1.sync.aligned.b32 %0, %1;" :: "r"(t), "r"((uint32_t)(n)))
#define TCGEN05_RELINQUISH() \
    asm volatile("tcgen05.relinquish_alloc_permit.cta_group::1.sync.aligned;")
#define TCGEN05_COMMIT(mb) \
    asm volatile("tcgen05.commit.cta_group::1.mbarrier::arrive::one.shared::cluster.b64 [%0];" \
                 :: "r"(mb) : "memory")
#define TCGEN05_FENCE_AFTER() asm volatile("tcgen05.fence::after_thread_sync;" ::: "memory")
#define TCGEN05_FENCE_BEFORE() asm volatile("tcgen05.fence::before_thread_sync;" ::: "memory")
#define TCGEN05_WAIT_LD() asm volatile("tcgen05.wait::ld.sync.aligned;" ::: "memory")
#define FENCE_PROXY_ASYNC() asm volatile("fence.proxy.async.shared::cta;" ::: "memory")

#define LDTM_X32(r, a) \
    asm volatile("tcgen05.ld.sync.aligned.32x32b.x32.b32 "                     \
        "{%0,%1,%2,%3,%4,%5,%6,%7,%8,%9,%10,%11,%12,%13,%14,%15,"              \
        "%16,%17,%18,%19,%20,%21,%22,%23,%24,%25,%26,%27,%28,%29,%30,%31}, [%32];" \
        : "=r"((r)[0]), "=r"((r)[1]), "=r"((r)[2]), "=r"((r)[3]),              \
          "=r"((r)[4]), "=r"((r)[5]), "=r"((r)[6]), "=r"((r)[7]),              \
          "=r"((r)[8]), "=r"((r)[9]), "=r"((r)[10]), "=r"((r)[11]),            \
          "=r"((r)[12]), "=r"((r)[13]), "=r"((r)[14]), "=r"((r)[15]),          \
          "=r"((r)[16]), "=r"((r)[17]), "=r"((r)[18]), "=r"((r)[19]),          \
          "=r"((r)[20]), "=r"((r)[21]), "=r"((r)[22]), "=r"((r)[23]),          \
          "=r"((r)[24]), "=r"((r)[25]), "=r"((r)[26]), "=r"((r)[27]),          \
          "=r"((r)[28]), "=r"((r)[29]), "=r"((r)[30]), "=r"((r)[31])           \
        : "r"(a))

__device__ __forceinline__ void mma_f16_ss(uint32_t d, uint64_t ad, uint64_t bd,
                                           uint32_t idesc, uint32_t en) {
    asm volatile(
        "{\n\t.reg .pred p;\n\tsetp.ne.u32 p, %5, 0;\n\t"
        "tcgen05.mma.cta_group::1.kind::f16 [%0], %1, %2, %3, {%4,%4,%4,%4}, p;\n\t}"
        :: "r"(d), "l"(ad), "l"(bd), "r"(idesc), "r"(0u), "r"(en) : "memory");
}
#endif  // HAS_TCGEN05

// mbarrier layout: full[s] at sb+8+s*16, empty[s] at sb+16+s*16, done at sb+8+S*16
#define FULLB(sb, s)  ((sb) + 8 + (s) * 16)
#define EMPTYB(sb, s) ((sb) + 16 + (s) * 16)
#define DONEB(sb)     ((sb) + 8 + STAGES * 16)

__global__ void __launch_bounds__(NT, 1)
gemm_tc(const float* __restrict__ bias, float* __restrict__ Y) {
#if HAS_TCGEN05
    extern __shared__ __align__(1024) char smem[];
    const uint32_t sb = smem_u32(smem);
    const int tid = threadIdx.x;
    const int wid = tid >> 5;
    const int lane = tid & 31;
    const int m0 = blockIdx.y * BM;
    const int n0 = blockIdx.x * BN;

    if (wid == 8) TCGEN05_ALLOC(sb, 512);
    if (tid == 0) {
#pragma unroll
        for (int s = 0; s < STAGES; s++) {
            MBARRIER_INIT(FULLB(sb, s), 256);   // one arrive per producer thread
            MBARRIER_INIT(EMPTYB(sb, s), 1);    // tcgen05.commit arrives one
        }
        MBARRIER_INIT(DONEB(sb), 1);
    }
    __syncthreads();
    uint32_t tmem;
    asm volatile("ld.shared.b32 %0, [%1];" : "=r"(tmem) : "r"(sb));

    if (wid < 8) {
        // ---------------- producers: warps 0-7 (256 threads) ----------------
        const int row8 = tid >> 3;        // 0..31 -> covers 256 rows over 8 iters
        const int c    = tid & 7;         // 16B chunk within 128B row (8 halves)
        const __half* Xp = g_X + (size_t)m0 * IN_F;
        const __half* Wp = g_W + (size_t)n0 * IN_F;
        for (int kt = 0; kt < NKI; kt++) {
            const int b = kt % STAGES;
            if (kt >= STAGES)
                MBARRIER_WAIT_PARITY(EMPTYB(sb, b), (uint32_t)((kt / STAGES + 1) & 1));
            const uint32_t abase = sb + SMEM_STAGE0 + b * STAGE_BYTES;
            const uint32_t bbase = abase + 32768;
            const size_t ko = (size_t)kt * KC;
#pragma unroll
            for (int i = 0; i < 8; i++) {
                const int row = i * 32 + row8;
                const uint32_t sw = (uint32_t)(row * 128 + ((c ^ (row & 7)) << 4));
                CP_ASYNC16(abase + sw,
                           __cvta_generic_to_global(Xp + (size_t)row * IN_F + ko + c * 8));
            }
#pragma unroll
            for (int i = 0; i < 8; i++) {
                const int row = i * 32 + row8;
                const uint32_t sw = (uint32_t)(row * 128 + ((c ^ (row & 7)) << 4));
                CP_ASYNC16(bbase + sw,
                           __cvta_generic_to_global(Wp + (size_t)row * IN_F + ko + c * 8));
            }
            CP_ASYNC_MBAR_ARRIVE(FULLB(sb, b));
        }
    } else if (tid == 256) {
        // ---------------- MMA issuer: one thread of warp 8 ----------------
        for (int kt = 0; kt < NKI; kt++) {
            const int b = kt % STAGES;
            MBARRIER_WAIT_PARITY(FULLB(sb, b), (uint32_t)((kt / STAGES) & 1));
            FENCE_PROXY_ASYNC();
            const uint32_t ss = sb + SMEM_STAGE0 + b * STAGE_BYTES;
            const uint64_t a0 = MAKE_DESC(ss);
            const uint64_t a1 = MAKE_DESC(ss + 16384);   // A rows 128-255
            const uint64_t bd = MAKE_DESC(ss + 32768);
#pragma unroll
            for (int ks = 0; ks < 4; ks++) {             // 4 x K=16 within 128B row
                const uint32_t en = (kt > 0 || ks > 0) ? 1u : 0u;
                mma_f16_ss(tmem,       a0 + ks * 2, bd + ks * 2, MMA_IDESC, en);
                mma_f16_ss(tmem + 256, a1 + ks * 2, bd + ks * 2, MMA_IDESC, en);
            }
            TCGEN05_COMMIT(EMPTYB(sb, b));               // frees buffer b for producers
        }
        TCGEN05_COMMIT(DONEB(sb));                       // in-order: fires when ALL MMAs done
    }

    // ---------------- epilogue: warps 8-11 ----------------
    if (wid >= 8) {
        MBARRIER_WAIT_PARITY(DONEB(sb), 0u);
        TCGEN05_FENCE_AFTER();
        const int wid2 = wid - 8;
#pragma unroll
        for (int half = 0; half < 2; half++) {
            const int m = m0 + half * 128 + wid2 * 32 + lane;
            float* yrow = Y + (size_t)m * OUT_F + n0;
#pragma unroll
            for (int c0 = 0; c0 < 256; c0 += 32) {
                uint32_t r[32];
                LDTM_X32(r, tmem + half * 256 + c0);
                TCGEN05_WAIT_LD();
                const float* bp = bias + n0 + c0;
#pragma unroll
                for (int j = 0; j < 32; j += 4) {
                    float4 v;
                    v.x = __uint_as_float(r[j + 0]) + bp[j + 0];
                    v.y = __uint_as_float(r[j + 1]) + bp[j + 1];
                    v.z = __uint_as_float(r[j + 2]) + bp[j + 2];
                    v.w = __uint_as_float(r[j + 3]) + bp[j + 3];
                    *reinterpret_cast<float4*>(yrow + c0 + j) = v;
                }
            }
        }
        TCGEN05_FENCE_BEFORE();
    }

    __syncthreads();
    if (tid == 0) {
#pragma unroll
        for (int s = 0; s < STAGES; s++) {
            MBARRIER_INVAL(FULLB(sb, s));
            MBARRIER_INVAL(EMPTYB(sb, s));
        }
        MBARRIER_INVAL(DONEB(sb));
    }
    __syncthreads();
    if (wid == 8) {
        TCGEN05_RELINQUISH();
        TCGEN05_DEALLOC(tmem, 512);
    }
#endif  // HAS_TCGEN05
}

// ---------------------------------------------------------------- launch
extern "C" void kernel_launch(void* const* d_in, const int* in_sizes, int n_in,
                              void* d_out, int out_size) {
    const float* x       = (const float*)d_in[0];
    const int*   packed  = (const int*)d_in[1];
    const float* scales  = (const float*)d_in[2];
    const float* offsets = (const float*)d_in[3];
    const float* bias    = (const float*)d_in[4];
    float* out = (float*)d_out;

    // fused prepass: X fp16-round (32768 blocks) + W dequant (32768 blocks)
    prepass_kernel<<<65536, 256>>>(x, packed, scales, offsets);

    // main GEMM: 256x256 CTA tiles, tcgen05 fp16, warp-specialized pipeline
    static bool attr_set = false;
    if (!attr_set) {
        cudaFuncSetAttribute(gemm_tc, cudaFuncAttributeMaxDynamicSharedMemorySize, SMEM_TOTAL);
        attr_set = true;
    }
    dim3 grid(OUT_F / BN, M_TOT / BM);   // (16, 32)
    gemm_tc<<<grid, NT, SMEM_TOTAL>>>(bias, out);
}